// round 14
// baseline (speedup 1.0000x reference)
#include <cuda_runtime.h>
#include <cuda_bf16.h>
#include <cstdint>

#define NPIX (512*512)
#define CZ 128
#define CT 64
#define NTPL 4
#define NH 4
#define DH 32

// ---------------- device scratch ----------------
__device__ __align__(256) float g_U[(size_t)NPIX * 256];       // 256 MB fp32
// combined weights, bf16 hi/lo, [n][k] row-major
__device__ __align__(256) __nv_bfloat16 g_W1h[2 * 128 * 128];  // [nh][n][kz]
__device__ __align__(256) __nv_bfloat16 g_W1l[2 * 128 * 128];
__device__ __align__(256) __nv_bfloat16 g_W2h[128 * 256];      // [n][kk]
__device__ __align__(256) __nv_bfloat16 g_W2l[128 * 256];

// ---------------- helpers ----------------
__device__ __forceinline__ uint32_t smem_u32(const void* p) {
    uint32_t a;
    asm("{ .reg .u64 t; cvta.to.shared.u64 t, %1; cvt.u32.u64 %0, t; }" : "=r"(a) : "l"(p));
    return a;
}
__device__ __forceinline__ void ldx4(uint32_t r[4], uint32_t addr) {
    asm volatile("ldmatrix.sync.aligned.m8n8.x4.shared.b16 {%0,%1,%2,%3}, [%4];"
                 : "=r"(r[0]), "=r"(r[1]), "=r"(r[2]), "=r"(r[3]) : "r"(addr));
}
__device__ __forceinline__ void mma16816(float c[4], const uint32_t a[4],
                                         uint32_t b0, uint32_t b1) {
    asm volatile(
        "mma.sync.aligned.m16n8k16.row.col.f32.bf16.bf16.f32 "
        "{%0,%1,%2,%3}, {%4,%5,%6,%7}, {%8,%9}, {%0,%1,%2,%3};"
        : "+f"(c[0]), "+f"(c[1]), "+f"(c[2]), "+f"(c[3])
        : "r"(a[0]), "r"(a[1]), "r"(a[2]), "r"(a[3]), "r"(b0), "r"(b1));
}
__device__ __forceinline__ uint32_t pack_bf2(float x, float y) {
    __nv_bfloat162 p = __halves2bfloat162(__float2bfloat16(x), __float2bfloat16(y));
    return *(uint32_t*)&p;
}
__device__ __forceinline__ void cp16(uint32_t dst, const void* src) {
    asm volatile("cp.async.cg.shared.global [%0], [%1], 16;" :: "r"(dst), "l"(src));
}
__device__ __forceinline__ void cp_commit() { asm volatile("cp.async.commit_group;"); }
__device__ __forceinline__ void cp_wait0() {
    asm volatile("cp.async.wait_group 0;" ::: "memory");
}

// ---------------- prep: combined weights, bf16 hi/lo split ----------------
__global__ void prep_kernel(const float* __restrict__ wq, const float* __restrict__ wk,
                            const float* __restrict__ wv, const float* __restrict__ wo) {
    int id = blockIdx.x * blockDim.x + threadIdx.x;
    float val;
    __nv_bfloat16 *dh, *dl;
    int idx;
    if (id < 32768) {
        int kz = id & 127, n = (id >> 7) & 127, nh = id >> 14;
        int hc = nh * 128 + n;
        int h = hc >> 6, c = hc & 63;
        float s = 0.f;
#pragma unroll
        for (int dd = 0; dd < DH; ++dd)
            s += wq[kz * CZ + h * DH + dd] * wk[c * CZ + h * DH + dd];
        val = s * 0.17677669529663687f;
        dh = g_W1h; dl = g_W1l; idx = id;
    } else {
        int e = id - 32768;
        int kk = e & 255, n = e >> 8;
        int h = kk >> 6, c = kk & 63;
        float s = 0.f;
#pragma unroll
        for (int dd = 0; dd < DH; ++dd)
            s += wv[c * CZ + h * DH + dd] * wo[(h * DH + dd) * CZ + n];
        val = s;
        dh = g_W2h; dl = g_W2l; idx = e;
    }
    __nv_bfloat16 hi = __float2bfloat16(val);
    __nv_bfloat16 lo = __float2bfloat16(val - __bfloat162float(hi));
    dh[idx] = hi;
    dl[idx] = lo;
}

// ---------------- inner chunk for 64-wide M warp tile (G1) ----------------
__device__ __forceinline__ void chunk_mma(
    uint32_t aBh, uint32_t aBl, uint32_t wBh, uint32_t wBl, uint32_t kAbase,
    float acc[4][4][4], int lrow, int lkb, int mw, int nw) {
#pragma unroll
    for (int k16 = 0; k16 < 2; ++k16) {
        const uint32_t kb = (uint32_t)(k16 * 32 + lkb);
        uint32_t bh[2][4], bl[2][4];
#pragma unroll
        for (int ng = 0; ng < 2; ++ng) {
            uint32_t off = (uint32_t)(nw * 32 + ng * 16 + lrow) * 80 + kb;
            ldx4(bh[ng], wBh + off);
            ldx4(bl[ng], wBl + off);
        }
        uint32_t ah[2][4], al[2][4];
        {
            uint32_t off = (uint32_t)(mw * 64 + lrow) * 80 + kAbase + kb;
            ldx4(ah[0], aBh + off);
            ldx4(al[0], aBl + off);
        }
#pragma unroll
        for (int mb = 0; mb < 4; ++mb) {
            const int cur = mb & 1;
            if (mb < 3) {
                uint32_t off =
                    (uint32_t)(mw * 64 + (mb + 1) * 16 + lrow) * 80 + kAbase + kb;
                ldx4(ah[cur ^ 1], aBh + off);
                ldx4(al[cur ^ 1], aBl + off);
            }
#pragma unroll
            for (int nb = 0; nb < 4; ++nb) {
                const int ng = nb >> 1, hf = nb & 1;
                mma16816(acc[mb][nb], ah[cur], bh[ng][hf], bh[ng][2 + hf]);
                mma16816(acc[mb][nb], ah[cur], bl[ng][hf], bl[ng][2 + hf]);
                mma16816(acc[mb][nb], al[cur], bh[ng][hf], bh[ng][2 + hf]);
            }
        }
    }
}

// ---------------- inner chunk for 32-wide M warp tile (fused G2) ----------------
__device__ __forceinline__ void chunk_mma32(
    uint32_t aBh, uint32_t aBl, uint32_t wBh, uint32_t wBl,
    float acc[2][4][4], int lrow, int lkb, int mw, int nw) {
#pragma unroll
    for (int k16 = 0; k16 < 2; ++k16) {
        const uint32_t kb = (uint32_t)(k16 * 32 + lkb);
        uint32_t bh[2][4], bl[2][4];
#pragma unroll
        for (int ng = 0; ng < 2; ++ng) {
            uint32_t off = (uint32_t)(nw * 32 + ng * 16 + lrow) * 80 + kb;
            ldx4(bh[ng], wBh + off);
            ldx4(bl[ng], wBl + off);
        }
        uint32_t ah[2][4], al[2][4];
#pragma unroll
        for (int mb = 0; mb < 2; ++mb) {
            uint32_t off = (uint32_t)(mw * 32 + mb * 16 + lrow) * 80 + kb;
            ldx4(ah[mb], aBh + off);
            ldx4(al[mb], aBl + off);
        }
#pragma unroll
        for (int mb = 0; mb < 2; ++mb)
#pragma unroll
            for (int nb = 0; nb < 4; ++nb) {
                const int ng = nb >> 1, hf = nb & 1;
                mma16816(acc[mb][nb], ah[mb], bh[ng][hf], bh[ng][2 + hf]);
                mma16816(acc[mb][nb], ah[mb], bl[ng][hf], bl[ng][2 + hf]);
                mma16816(acc[mb][nb], al[mb], bh[ng][hf], bh[ng][2 + hf]);
            }
    }
}

// ===================== GEMM1: U = Z @ W1, fp32 z in, in-smem split (unchanged) ========
static constexpr int G1_AL = 10240;
static constexpr int G1_W = 20480;
static constexpr int G1_STG = 61440;
static constexpr int G1SMEM = 77824;

__global__ __launch_bounds__(256, 2) void gemm1_kernel(const float* __restrict__ z) {
    extern __shared__ char sm[];
    const uint32_t sbase = smem_u32(sm);
    const int tid = threadIdx.x;
    const int lane = tid & 31;
    const int wid = tid >> 5;
    const int mw = wid & 1, nw = wid >> 1;
    const int pb = blockIdx.x * 128;
    const int nh = blockIdx.y;

    const __nv_bfloat16* __restrict__ Wh = g_W1h + nh * 16384;
    const __nv_bfloat16* __restrict__ Wl = g_W1l + nh * 16384;

    auto issue = [&](int kt, int s) {
#pragma unroll
        for (int i = 0; i < 4; ++i) {
            int id = tid + 256 * i;
            int r = id >> 3, c = id & 7;
            cp16(sbase + (uint32_t)(G1_STG + r * 128 + c * 16),
                 z + (size_t)(pb + r) * 128 + kt * 32 + c * 4);
        }
#pragma unroll
        for (int i = 0; i < 4; ++i) {
            int id = tid + 256 * i;
            int plane = id >> 9;
            int r = (id >> 2) & 127;
            int c = id & 3;
            cp16(sbase + (uint32_t)(G1_W + (s * 2 + plane) * 10240 + r * 80 + c * 16),
                 (plane ? Wl : Wh) + (size_t)r * 128 + kt * 32 + c * 8);
        }
        cp_commit();
    };

    float acc[4][4][4];
#pragma unroll
    for (int i = 0; i < 4; ++i)
#pragma unroll
        for (int j = 0; j < 4; ++j)
#pragma unroll
            for (int q = 0; q < 4; ++q) acc[i][j][q] = 0.f;

    const int lrow = lane & 15;
    const int lkb = (lane >> 4) * 16;

    issue(0, 0);

#pragma unroll
    for (int kt = 0; kt < 4; ++kt) {
        const int s = kt & 1;
        cp_wait0();
        __syncthreads();

        {
            int r = tid >> 1, half = tid & 1;
            const float4* src = (const float4*)(sm + G1_STG + r * 128 + half * 64);
#pragma unroll
            for (int j = 0; j < 4; ++j) {
                float4 v = src[j];
                __nv_bfloat16 h0 = __float2bfloat16(v.x), h1 = __float2bfloat16(v.y);
                __nv_bfloat16 h2 = __float2bfloat16(v.z), h3 = __float2bfloat16(v.w);
                uint32_t hw0 = pack_bf2(v.x, v.y);
                uint32_t hw1 = pack_bf2(v.z, v.w);
                uint32_t lw0 = pack_bf2(v.x - __bfloat162float(h0),
                                        v.y - __bfloat162float(h1));
                uint32_t lw1 = pack_bf2(v.z - __bfloat162float(h2),
                                        v.w - __bfloat162float(h3));
                uint32_t base = (uint32_t)(r * 80 + half * 32 + j * 8);
                *(uint32_t*)(sm + base) = hw0;
                *(uint32_t*)(sm + base + 4) = hw1;
                *(uint32_t*)(sm + G1_AL + base) = lw0;
                *(uint32_t*)(sm + G1_AL + base + 4) = lw1;
            }
        }
        __syncthreads();

        if (kt < 3) issue(kt + 1, s ^ 1);

        chunk_mma(sbase, sbase + G1_AL,
                  sbase + (uint32_t)(G1_W + s * 2 * 10240),
                  sbase + (uint32_t)(G1_W + s * 2 * 10240 + 10240),
                  0, acc, lrow, lkb, mw, nw);
    }

    const int r4 = lane >> 2, c2 = (lane & 3) * 2;
#pragma unroll
    for (int mb = 0; mb < 4; ++mb)
#pragma unroll
        for (int nb = 0; nb < 4; ++nb) {
            int row = pb + mw * 64 + mb * 16 + r4;
            int col = nh * 128 + nw * 32 + nb * 8 + c2;
            *(float2*)(&g_U[(size_t)row * 256 + col]) =
                make_float2(acc[mb][nb][0], acc[mb][nb][1]);
            *(float2*)(&g_U[(size_t)(row + 8) * 256 + col]) =
                make_float2(acc[mb][nb][2], acc[mb][nb][3]);
        }
}

// ===================== fused attention + GEMM2: U,t -> M(smem) -> out ================
// 64 pixels/CTA, 256 threads (warps 2(M)x4(N), warp tile 32x32), K=256 as 8 chunks.
// smem: AH @0 (4 chunks x 64 x 80 = 20480), AL @20480, W 2stage x 2plane @40960 (40960).
static constexpr int F_AL = 20480;
static constexpr int F_W = 40960;
static constexpr int F_SMEM = 81920;

__global__ __launch_bounds__(256, 2) void gemm2_fused(
    const float* __restrict__ t, const float* __restrict__ mask,
    const float* __restrict__ bias, float* __restrict__ Cout) {
    extern __shared__ char sm[];
    const uint32_t sbase = smem_u32(sm);
    const int tid = threadIdx.x;
    const int lane = tid & 31;
    const int wid = tid >> 5;
    const int mw = wid & 1, nw = wid >> 1;
    const int pb = blockIdx.x * 64;

    auto issueW = [&](int kt, int s) {
#pragma unroll
        for (int i = 0; i < 4; ++i) {
            int id = tid + 256 * i;          // 0..1023
            int plane = id >> 9;
            int rr = id & 511;
            int r = rr >> 2, c = rr & 3;
            cp16(sbase + (uint32_t)(F_W + s * 20480 + plane * 10240 + r * 80 + c * 16),
                 (plane ? g_W2l : g_W2h) + (size_t)r * 256 + kt * 32 + c * 8);
        }
        cp_commit();
    };

    // prefetch W chunk 0 while attention computes
    issueW(0, 0);

    // ---- attention prologue: 8 pixels per warp ----
    float mbias[NTPL];
#pragma unroll
    for (int nt = 0; nt < NTPL; ++nt)
        mbias[nt] = 100000.0f * (__ldg(mask + nt) - 1.0f);

    const uint32_t choff = (lane >= 16) ? 5120u : 0u;   // second half-warp -> next chunk
    const uint32_t kkb = (uint32_t)((2 * lane) & 31) * 2;

    uint32_t sh[8][2], sl[8][2];  // stash for cols 128..255 (h = 2,3)

#pragma unroll 1
    for (int i = 0; i < 8; ++i) {
        int row = wid * 8 + i;
        int p = pb + row;
        float2 u[NH];
#pragma unroll
        for (int h = 0; h < NH; ++h)
            u[h] = *(const float2*)(g_U + (size_t)p * 256 + h * 64 + 2 * lane);
        float2 tt[NTPL];
#pragma unroll
        for (int nt = 0; nt < NTPL; ++nt)
            tt[nt] = *(const float2*)(t + ((size_t)nt * NPIX + p) * CT + 2 * lane);

        float lg[NH][NTPL];
#pragma unroll
        for (int h = 0; h < NH; ++h)
#pragma unroll
            for (int nt = 0; nt < NTPL; ++nt)
                lg[h][nt] = u[h].x * tt[nt].x + u[h].y * tt[nt].y;
#pragma unroll
        for (int off = 16; off > 0; off >>= 1)
#pragma unroll
            for (int h = 0; h < NH; ++h)
#pragma unroll
                for (int nt = 0; nt < NTPL; ++nt)
                    lg[h][nt] += __shfl_xor_sync(0xFFFFFFFFu, lg[h][nt], off);

        float at[NH][NTPL];
#pragma unroll
        for (int h = 0; h < NH; ++h) {
            float l0 = lg[h][0] + mbias[0], l1 = lg[h][1] + mbias[1];
            float l2 = lg[h][2] + mbias[2], l3 = lg[h][3] + mbias[3];
            float mx = fmaxf(fmaxf(l0, l1), fmaxf(l2, l3));
            float e0 = __expf(l0 - mx), e1 = __expf(l1 - mx);
            float e2 = __expf(l2 - mx), e3 = __expf(l3 - mx);
            float inv = __fdividef(1.0f, e0 + e1 + e2 + e3);
            at[h][0] = e0 * inv; at[h][1] = e1 * inv;
            at[h][2] = e2 * inv; at[h][3] = e3 * inv;
        }

#pragma unroll
        for (int h = 0; h < NH; ++h) {
            float mx = at[h][0] * tt[0].x + at[h][1] * tt[1].x +
                       at[h][2] * tt[2].x + at[h][3] * tt[3].x;
            float my = at[h][0] * tt[0].y + at[h][1] * tt[1].y +
                       at[h][2] * tt[2].y + at[h][3] * tt[3].y;
            __nv_bfloat16 hx = __float2bfloat16(mx), hy = __float2bfloat16(my);
            uint32_t hi = pack_bf2(mx, my);
            uint32_t lo = pack_bf2(mx - __bfloat162float(hx),
                                   my - __bfloat162float(hy));
            if (h < 2) {
                uint32_t a = (uint32_t)(h * 2) * 5120u + choff
                           + (uint32_t)row * 80 + kkb;
                *(uint32_t*)(sm + a) = hi;
                *(uint32_t*)(sm + F_AL + a) = lo;
            } else {
                sh[i][h - 2] = hi;
                sl[i][h - 2] = lo;
            }
        }
    }
    __syncthreads();

    // ---- GEMM mainloop: 8 chunks, A resident (4-chunk window), W double-buffered ----
    float acc[2][4][4];
#pragma unroll
    for (int i = 0; i < 2; ++i)
#pragma unroll
        for (int j = 0; j < 4; ++j)
#pragma unroll
            for (int q = 0; q < 4; ++q) acc[i][j][q] = 0.f;

    const int lrow = lane & 15;
    const int lkb = (lane >> 4) * 16;

#pragma unroll
    for (int kt = 0; kt < 8; ++kt) {
        const int s = kt & 1;
        cp_wait0();
        __syncthreads();
        if (kt == 4) {
            // overwrite A chunks with stashed cols 128..255 (h = 2,3)
#pragma unroll
            for (int i = 0; i < 8; ++i) {
                int row = wid * 8 + i;
#pragma unroll
                for (int hh = 0; hh < 2; ++hh) {
                    uint32_t a = (uint32_t)(hh * 2) * 5120u + choff
                               + (uint32_t)row * 80 + kkb;
                    *(uint32_t*)(sm + a) = sh[i][hh];
                    *(uint32_t*)(sm + F_AL + a) = sl[i][hh];
                }
            }
            __syncthreads();
        }
        if (kt < 7) issueW(kt + 1, s ^ 1);

        chunk_mma32(sbase + (uint32_t)((kt & 3) * 5120),
                    sbase + (uint32_t)(F_AL + (kt & 3) * 5120),
                    sbase + (uint32_t)(F_W + s * 20480),
                    sbase + (uint32_t)(F_W + s * 20480 + 10240),
                    acc, lrow, lkb, mw, nw);
    }

    // ---- epilogue ----
    const int r4 = lane >> 2, c2 = (lane & 3) * 2;
#pragma unroll
    for (int mb = 0; mb < 2; ++mb)
#pragma unroll
        for (int nb = 0; nb < 4; ++nb) {
            int row = pb + mw * 32 + mb * 16 + r4;
            int col = nw * 32 + nb * 8 + c2;
            float2 b = *(const float2*)(bias + col);
            float2 v0 = make_float2(acc[mb][nb][0] + b.x, acc[mb][nb][1] + b.y);
            float2 v1 = make_float2(acc[mb][nb][2] + b.x, acc[mb][nb][3] + b.y);
            *(float2*)(&Cout[(size_t)row * 128 + col]) = v0;
            *(float2*)(&Cout[(size_t)(row + 8) * 128 + col]) = v1;
        }
}

// ---------------- launch ----------------
extern "C" void kernel_launch(void* const* d_in, const int* in_sizes, int n_in,
                              void* d_out, int out_size) {
    const float* t    = (const float*)d_in[0];
    const float* z    = (const float*)d_in[1];
    const float* mask = (const float*)d_in[2];
    const float* wq   = (const float*)d_in[3];
    const float* wk   = (const float*)d_in[4];
    const float* wv   = (const float*)d_in[5];
    const float* wo   = (const float*)d_in[6];
    const float* bo   = (const float*)d_in[7];
    float* out = (float*)d_out;

    cudaFuncSetAttribute(gemm1_kernel,
                         cudaFuncAttributeMaxDynamicSharedMemorySize, G1SMEM);
    cudaFuncSetAttribute(gemm2_fused,
                         cudaFuncAttributeMaxDynamicSharedMemorySize, F_SMEM);

    // 1. weights precombine + bf16 hi/lo split
    prep_kernel<<<256, 256>>>(wq, wk, wv, wo);

    // 2. U = Z @ Ac (fp32 z in, in-smem hi/lo split; fp32 U out)
    gemm1_kernel<<<dim3(NPIX / 128, 2), 256, G1SMEM>>>(z);

    // 3. fused: attention (U, t, mask -> M in smem) + out = M @ Bc + bo
    gemm2_fused<<<NPIX / 64, 256, F_SMEM>>>(t, mask, bo, out);
}